// round 3
// baseline (speedup 1.0000x reference)
#include <cuda_runtime.h>
#include <cuda_bf16.h>
#include <math.h>

// Problem constants (fixed by setup_inputs)
#define UU 100000
#define BB 128
#define KK 500
#define NNBH 100
#define NRUNS 10

// PRNG mode: 1 = partitionable (per-element 64-bit counter, o0^o1),
//            0 = legacy (iota(2N) split in halves)
// R1 evidence: rel_err 1.06e-3 == expected error for fully-wrong choices -> use legacy.
#define THREEFRY_PARTITIONABLE 0

// ---------------- scratch (no allocations allowed) ----------------
__device__ float  g_y[NRUNS][KK][BB];     // centered+normalized rows (x - mean)/||x-mean||
__device__ float2 g_pos[NRUNS][KK];
__device__ double g_acc[NRUNS][5];        // Sr, Srr, Srd, Sd, Sdd

// ---------------- threefry2x32 (JAX-exact) ----------------
__device__ __forceinline__ unsigned rotl32(unsigned x, int r) {
    return (x << r) | (x >> (32 - r));
}

__device__ __forceinline__ void tf2x32(unsigned x0, unsigned x1,
                                       unsigned& o0, unsigned& o1) {
    const unsigned k0 = 0u, k1 = 42u;             // jax.random.key(42) -> [0, 42]
    const unsigned k2 = k0 ^ k1 ^ 0x1BD11BDAu;
    x0 += k0; x1 += k1;
    const int rotA[4] = {13, 15, 26, 6};
    const int rotB[4] = {17, 29, 16, 24};
#pragma unroll
    for (int i = 0; i < 4; i++) { x0 += x1; x1 = rotl32(x1, rotA[i]); x1 ^= x0; }
    x0 += k1; x1 += k2 + 1u;
#pragma unroll
    for (int i = 0; i < 4; i++) { x0 += x1; x1 = rotl32(x1, rotB[i]); x1 ^= x0; }
    x0 += k2; x1 += k0 + 2u;
#pragma unroll
    for (int i = 0; i < 4; i++) { x0 += x1; x1 = rotl32(x1, rotA[i]); x1 ^= x0; }
    x0 += k0; x1 += k1 + 3u;
#pragma unroll
    for (int i = 0; i < 4; i++) { x0 += x1; x1 = rotl32(x1, rotB[i]); x1 ^= x0; }
    x0 += k1; x1 += k2 + 4u;
#pragma unroll
    for (int i = 0; i < 4; i++) { x0 += x1; x1 = rotl32(x1, rotA[i]); x1 ^= x0; }
    x0 += k2; x1 += k0 + 5u;
    o0 = x0; o1 = x1;
}

__device__ __forceinline__ unsigned choice_for(int r) {
    unsigned hi, lo;
#if THREEFRY_PARTITIONABLE
    unsigned a0, a1, b0, b1;
    tf2x32(0u, (unsigned)r, a0, a1);           hi = a0 ^ a1;
    tf2x32(0u, (unsigned)(r + NRUNS), b0, b1); lo = b0 ^ b1;
#else
    // legacy: counts = iota(20), split halves -> x0 = r, x1 = r+10;
    // bits = concat(o0_all, o1_all).reshape(2,10): higher[r]=o0, lower[r]=o1
    unsigned a0, a1;
    tf2x32((unsigned)r, (unsigned)(r + NRUNS), a0, a1);
    hi = a0; lo = a1;
#endif
    // randint: multiplier = (2^16 % 100)^2 % 100 = 96
    return ((hi % 100u) * 96u + (lo % 100u)) % 100u;
}

// ---------------- kernel 1: gather + center + normalize ----------------
__global__ void k_gather(const float* __restrict__ feats,
                         const float* __restrict__ pos,
                         const int* __restrict__ neigh) {
    int run = blockIdx.y;
    int sub = blockIdx.x;
    __shared__ int s_choice;
    if (threadIdx.x == 0) s_choice = (int)choice_for(run);
    if (sub == 0 && threadIdx.x < 5) g_acc[run][threadIdx.x] = 0.0;
    __syncthreads();
    int choice = s_choice;
    int warp = threadIdx.x >> 5, lane = threadIdx.x & 31;

#pragma unroll
    for (int it = 0; it < 4; it++) {
        int k = sub * 32 + it * 8 + warp;
        if (k >= KK) continue;
        int u = __ldg(&neigh[choice * KK + k]);
        float v0 = __ldg(&feats[(size_t)(lane      ) * UU + u]);
        float v1 = __ldg(&feats[(size_t)(lane + 32) * UU + u]);
        float v2 = __ldg(&feats[(size_t)(lane + 64) * UU + u]);
        float v3 = __ldg(&feats[(size_t)(lane + 96) * UU + u]);
        float s = v0 + v1 + v2 + v3;
#pragma unroll
        for (int o = 16; o; o >>= 1) s += __shfl_xor_sync(0xFFFFFFFFu, s, o);
        float mean = s * (1.0f / 128.0f);
        float c0 = v0 - mean, c1 = v1 - mean, c2 = v2 - mean, c3 = v3 - mean;
        float ss = c0 * c0 + c1 * c1 + c2 * c2 + c3 * c3;
#pragma unroll
        for (int o = 16; o; o >>= 1) ss += __shfl_xor_sync(0xFFFFFFFFu, ss, o);
        float inv = rsqrtf(ss);
        g_y[run][k][lane     ] = c0 * inv;
        g_y[run][k][lane + 32] = c1 * inv;
        g_y[run][k][lane + 64] = c2 * inv;
        g_y[run][k][lane + 96] = c3 * inv;
        if (lane == 0) g_pos[run][k] = ((const float2*)pos)[u];
    }
}

// ---------------- kernel 2: lower-triangle pair sums ----------------
#define TI 50
#define NT 10
#define NTILE 55          // NT*(NT+1)/2
#define YSTR 132          // padded row stride (floats), multiple of 4, not 128
#define SMEM_BYTES (2 * TI * YSTR * 4 + 2 * TI * 8)

__global__ void __launch_bounds__(128, 4) k_pairs() {
    extern __shared__ float sm[];
    float* syi = sm;
    float* syj = sm + TI * YSTR;
    float2* sp = (float2*)(sm + 2 * TI * YSTR);   // [0..49]=pos_i, [50..99]=pos_j

    int run = blockIdx.x / NTILE;
    int t   = blockIdx.x % NTILE;
    int ti = 0;
    while ((ti + 1) * (ti + 2) / 2 <= t) ti++;
    int tj = t - ti * (ti + 1) / 2;
    int i0 = ti * TI, j0 = tj * TI;

    for (int idx = threadIdx.x; idx < TI * 32; idx += blockDim.x) {
        int r = idx >> 5, c4 = idx & 31;
        float4 vi = ((const float4*)&g_y[run][i0 + r][0])[c4];
        ((float4*)&syi[r * YSTR])[c4] = vi;
        float4 vj = ((const float4*)&g_y[run][j0 + r][0])[c4];
        ((float4*)&syj[r * YSTR])[c4] = vj;
    }
    if (threadIdx.x < TI)            sp[threadIdx.x]      = g_pos[run][i0 + threadIdx.x];
    else if (threadIdx.x < 2 * TI)   sp[threadIdx.x]      = g_pos[run][j0 + threadIdx.x - TI];
    __syncthreads();

    float sr = 0.f, srr = 0.f, srd = 0.f, sd = 0.f, sdd = 0.f;
    int tid = threadIdx.x;
    if (tid < 100) {
        int pi = tid / 10, pj = tid % 10;
        float acc[5][5];
#pragma unroll
        for (int a = 0; a < 5; a++)
#pragma unroll
            for (int b = 0; b < 5; b++) acc[a][b] = 0.f;

#pragma unroll 4
        for (int c = 0; c < 32; c++) {
            float4 A[5], Bv[5];
#pragma unroll
            for (int a = 0; a < 5; a++) A[a]  = ((float4*)&syi[(pi * 5 + a) * YSTR])[c];
#pragma unroll
            for (int b = 0; b < 5; b++) Bv[b] = ((float4*)&syj[(pj * 5 + b) * YSTR])[c];
#pragma unroll
            for (int a = 0; a < 5; a++)
#pragma unroll
                for (int b = 0; b < 5; b++) {
                    acc[a][b] += A[a].x * Bv[b].x + A[a].y * Bv[b].y
                               + A[a].z * Bv[b].z + A[a].w * Bv[b].w;
                }
        }

#pragma unroll
        for (int a = 0; a < 5; a++) {
#pragma unroll
            for (int b = 0; b < 5; b++) {
                int i = i0 + pi * 5 + a;
                int j = j0 + pj * 5 + b;
                if (i > j) {   // tril(k=-1); auto-true on off-diagonal tiles
                    float2 P = sp[pi * 5 + a];
                    float2 Q = sp[TI + pj * 5 + b];
                    float dx = P.x - Q.x, dy = P.y - Q.y;
                    float dist = sqrtf(dx * dx + dy * dy);
                    float ds = 1.0f / (dist + 1.0f);
                    float rv = acc[a][b];
                    sr  += rv;      srr += rv * rv;  srd += rv * ds;
                    sd  += ds;      sdd += ds * ds;
                }
            }
        }
    }

    float vals[5] = {sr, srr, srd, sd, sdd};
    __shared__ double red[4][5];
    int lane = tid & 31, wid = tid >> 5;
#pragma unroll
    for (int v = 0; v < 5; v++) {
        float x = vals[v];
#pragma unroll
        for (int o = 16; o; o >>= 1) x += __shfl_xor_sync(0xFFFFFFFFu, x, o);
        if (lane == 0) red[wid][v] = (double)x;
    }
    __syncthreads();
    if (tid < 5) {
        double s = red[0][tid] + red[1][tid] + red[2][tid] + red[3][tid];
        atomicAdd(&g_acc[run][tid], s);
    }
}

// ---------------- kernel 3: finalize Pearson + mean loss ----------------
__global__ void k_final(float* __restrict__ out) {
    __shared__ double losses[NRUNS];
    int r = threadIdx.x;
    if (r < NRUNS) {
        const double P = (double)(KK * (KK - 1) / 2);   // 124750
        double Sr  = g_acc[r][0], Srr = g_acc[r][1], Srd = g_acc[r][2];
        double Sd  = g_acc[r][3], Sdd = g_acc[r][4];
        double num = Srd - Sr * Sd / P;
        double den = sqrt((Srr - Sr * Sr / P) * (Sdd - Sd * Sd / P));
        double pear = num / den;
        losses[r] = (1.0 - pear) * 0.5;
    }
    __syncthreads();
    if (threadIdx.x == 0) {
        double s = 0.0;
        for (int i = 0; i < NRUNS; i++) s += losses[i];
        out[0] = (float)(s / NRUNS);
    }
}

// ---------------- launch ----------------
extern "C" void kernel_launch(void* const* d_in, const int* in_sizes, int n_in,
                              void* d_out, int out_size) {
    const float* feats = (const float*)d_in[0];   // (128, 100000) f32
    const float* pos   = (const float*)d_in[1];   // (100000, 2)   f32
    const int*   neigh = (const int*)  d_in[2];   // (100, 500)    i32

    cudaFuncSetAttribute(k_pairs, cudaFuncAttributeMaxDynamicSharedMemorySize,
                         SMEM_BYTES);

    k_gather<<<dim3(16, NRUNS), 256>>>(feats, pos, neigh);
    k_pairs<<<NRUNS * NTILE, 128, SMEM_BYTES>>>();
    k_final<<<1, 32>>>((float*)d_out);
}